// round 2
// baseline (speedup 1.0000x reference)
#include <cuda_runtime.h>
#include <math.h>

#define D_MODEL 1024
#define HEADS   16
#define DH      64
#define SEQ     1024
#define BATCH   8
#define MROWS   (BATCH*SEQ)   // 8192

// ---- scratch (no cudaMalloc allowed) ----
__device__ float g_Q[MROWS*D_MODEL];
__device__ float g_K[MROWS*D_MODEL];
__device__ float g_V[MROWS*D_MODEL];
__device__ float g_O[MROWS*D_MODEL];

// ============================================================
// SGEMM: C[M,N] = A[M,K] @ B[K,N], all row-major fp32.
// 128x128 tile, BK=16, 256 threads, 8x8 micro-tile per thread.
// ============================================================
__global__ __launch_bounds__(256) void sgemm128(
    const float* __restrict__ A, const float* __restrict__ B,
    float* __restrict__ C, int M, int N, int K)
{
    __shared__ float As[16][132];   // [k][m], padded
    __shared__ float Bs[16][128];   // [k][n]

    const int tid = threadIdx.x;
    const int m0 = blockIdx.y << 7;
    const int n0 = blockIdx.x << 7;
    const int ty = tid >> 4;        // 0..15
    const int tx = tid & 15;        // 0..15

    float acc[8][8];
    #pragma unroll
    for (int i = 0; i < 8; i++)
        #pragma unroll
        for (int j = 0; j < 8; j++) acc[i][j] = 0.f;

    for (int k0 = 0; k0 < K; k0 += 16) {
        // load A tile (128 rows x 16 cols) transposed into As[k][m]
        // load B tile (16 rows x 128 cols) straight into Bs[k][n]
        #pragma unroll
        for (int t = 0; t < 2; t++) {
            int f = tid + (t << 8);
            int ar = f >> 2, ac = (f & 3) << 2;
            float4 a4 = *(const float4*)&A[(m0 + ar) * K + k0 + ac];
            As[ac + 0][ar] = a4.x;
            As[ac + 1][ar] = a4.y;
            As[ac + 2][ar] = a4.z;
            As[ac + 3][ar] = a4.w;
            int br = f >> 5, bc = (f & 31) << 2;
            *(float4*)&Bs[br][bc] = *(const float4*)&B[(k0 + br) * N + n0 + bc];
        }
        __syncthreads();

        #pragma unroll
        for (int kk = 0; kk < 16; kk++) {
            float a[8], b[8];
            *(float4*)(a)     = *(float4*)&As[kk][ty * 8];
            *(float4*)(a + 4) = *(float4*)&As[kk][ty * 8 + 4];
            *(float4*)(b)     = *(float4*)&Bs[kk][tx * 8];
            *(float4*)(b + 4) = *(float4*)&Bs[kk][tx * 8 + 4];
            #pragma unroll
            for (int i = 0; i < 8; i++)
                #pragma unroll
                for (int j = 0; j < 8; j++)
                    acc[i][j] = fmaf(a[i], b[j], acc[i][j]);
        }
        __syncthreads();
    }

    #pragma unroll
    for (int i = 0; i < 8; i++) {
        float* cp = &C[(m0 + ty * 8 + i) * N + n0 + tx * 8];
        *(float4*)(cp)     = make_float4(acc[i][0], acc[i][1], acc[i][2], acc[i][3]);
        *(float4*)(cp + 4) = make_float4(acc[i][4], acc[i][5], acc[i][6], acc[i][7]);
    }
}

// ============================================================
// Flash attention, one CTA per (q-block of 64, head, batch).
// Q,K,V: [B*T, D_MODEL], head h occupies cols [h*64, h*64+64).
// Online softmax; S never hits gmem.
// ============================================================
#define PAD 68
#define ATT_SMEM (4 * 64 * PAD * sizeof(float))

__global__ __launch_bounds__(256) void attn64(
    const float* __restrict__ Q, const float* __restrict__ K,
    const float* __restrict__ V, float* __restrict__ O)
{
    extern __shared__ float sm[];
    float* Qd = sm;                 // [d][i], prescaled by 1/8
    float* Kd = sm + 64 * PAD;      // [d][j]
    float* Vs = sm + 2 * 64 * PAD;  // [j][c]
    float* Ss = sm + 3 * 64 * PAD;  // [i][j] scores -> P

    const int tid = threadIdx.x;
    const int qb = blockIdx.x;      // 0..15
    const int h  = blockIdx.y;      // 0..15
    const int b  = blockIdx.z;      // 0..7
    const int base = (b * SEQ) * D_MODEL + h * DH;

    const int ty = tid >> 4, tx = tid & 15;   // 16x16 for S micro-tiles
    const int rr = tid >> 2, c4 = tid & 3;    // 64x4 for softmax / O

    // load Q tile transposed [d][i], folding in 1/sqrt(dh)=1/8
    #pragma unroll
    for (int t = 0; t < 4; t++) {
        int f = tid + (t << 8);
        int i = f >> 4, d4 = (f & 15) << 2;
        float4 q = *(const float4*)&Q[base + (qb * 64 + i) * D_MODEL + d4];
        Qd[(d4 + 0) * PAD + i] = q.x * 0.125f;
        Qd[(d4 + 1) * PAD + i] = q.y * 0.125f;
        Qd[(d4 + 2) * PAD + i] = q.z * 0.125f;
        Qd[(d4 + 3) * PAD + i] = q.w * 0.125f;
    }

    float m_i = -1e30f, l_i = 0.f;
    float o[16];
    #pragma unroll
    for (int i = 0; i < 16; i++) o[i] = 0.f;

    for (int kb = 0; kb < SEQ / 64; kb++) {
        __syncthreads();  // previous iter's Vs/Ss reads done before overwrite
        // load K tile transposed [d][j], V tile natural [j][c]
        #pragma unroll
        for (int t = 0; t < 4; t++) {
            int f = tid + (t << 8);
            int j = f >> 4, d4 = (f & 15) << 2;
            float4 kv = *(const float4*)&K[base + (kb * 64 + j) * D_MODEL + d4];
            Kd[(d4 + 0) * PAD + j] = kv.x;
            Kd[(d4 + 1) * PAD + j] = kv.y;
            Kd[(d4 + 2) * PAD + j] = kv.z;
            Kd[(d4 + 3) * PAD + j] = kv.w;
            *(float4*)&Vs[j * PAD + d4] =
                *(const float4*)&V[base + (kb * 64 + j) * D_MODEL + d4];
        }
        __syncthreads();

        // ---- Phase A: S = (Q/8) @ K^T, 4x4 micro per thread ----
        float acc[4][4];
        #pragma unroll
        for (int u = 0; u < 4; u++)
            #pragma unroll
            for (int v = 0; v < 4; v++) acc[u][v] = 0.f;
        #pragma unroll
        for (int d = 0; d < 64; d++) {
            float4 q4 = *(float4*)&Qd[d * PAD + ty * 4];
            float4 k4 = *(float4*)&Kd[d * PAD + tx * 4];
            float qa[4] = {q4.x, q4.y, q4.z, q4.w};
            float ka[4] = {k4.x, k4.y, k4.z, k4.w};
            #pragma unroll
            for (int u = 0; u < 4; u++)
                #pragma unroll
                for (int v = 0; v < 4; v++)
                    acc[u][v] = fmaf(qa[u], ka[v], acc[u][v]);
        }
        #pragma unroll
        for (int u = 0; u < 4; u++)
            *(float4*)&Ss[(ty * 4 + u) * PAD + tx * 4] =
                make_float4(acc[u][0], acc[u][1], acc[u][2], acc[u][3]);
        __syncthreads();

        // ---- Phase B: online softmax, row rr, cols [c4*16, c4*16+16) ----
        float s[16];
        #pragma unroll
        for (int w = 0; w < 4; w++)
            *(float4*)(s + 4 * w) = *(float4*)&Ss[rr * PAD + c4 * 16 + 4 * w];
        float mx = s[0];
        #pragma unroll
        for (int i = 1; i < 16; i++) mx = fmaxf(mx, s[i]);
        mx = fmaxf(mx, __shfl_xor_sync(0xffffffffu, mx, 1));
        mx = fmaxf(mx, __shfl_xor_sync(0xffffffffu, mx, 2));
        float m_new = fmaxf(m_i, mx);
        float alpha = __expf(m_i - m_new);
        float lsum = 0.f;
        #pragma unroll
        for (int i = 0; i < 16; i++) {
            s[i] = __expf(s[i] - m_new);
            lsum += s[i];
        }
        lsum += __shfl_xor_sync(0xffffffffu, lsum, 1);
        lsum += __shfl_xor_sync(0xffffffffu, lsum, 2);
        l_i = l_i * alpha + lsum;
        m_i = m_new;
        #pragma unroll
        for (int i = 0; i < 16; i++) o[i] *= alpha;
        #pragma unroll
        for (int w = 0; w < 4; w++)
            *(float4*)&Ss[rr * PAD + c4 * 16 + 4 * w] =
                make_float4(s[4 * w], s[4 * w + 1], s[4 * w + 2], s[4 * w + 3]);
        __syncwarp();  // quad members read each other's P within the warp

        // ---- Phase C: O += P @ V ----
        #pragma unroll
        for (int j4 = 0; j4 < 16; j4++) {
            float4 p4 = *(float4*)&Ss[rr * PAD + j4 * 4];
            float pj[4] = {p4.x, p4.y, p4.z, p4.w};
            #pragma unroll
            for (int u = 0; u < 4; u++) {
                const float* vrow = &Vs[(j4 * 4 + u) * PAD + c4 * 16];
                #pragma unroll
                for (int w = 0; w < 4; w++) {
                    float4 v = *(const float4*)&vrow[4 * w];
                    o[4 * w + 0] = fmaf(pj[u], v.x, o[4 * w + 0]);
                    o[4 * w + 1] = fmaf(pj[u], v.y, o[4 * w + 1]);
                    o[4 * w + 2] = fmaf(pj[u], v.z, o[4 * w + 2]);
                    o[4 * w + 3] = fmaf(pj[u], v.w, o[4 * w + 3]);
                }
            }
        }
    }

    float inv = 1.f / l_i;
    float* op = &O[base + (qb * 64 + rr) * D_MODEL + c4 * 16];
    #pragma unroll
    for (int w = 0; w < 4; w++)
        *(float4*)&op[4 * w] = make_float4(o[4 * w] * inv, o[4 * w + 1] * inv,
                                           o[4 * w + 2] * inv, o[4 * w + 3] * inv);
}

// ============================================================
extern "C" void kernel_launch(void* const* d_in, const int* in_sizes, int n_in,
                              void* d_out, int out_size)
{
    const float* x  = (const float*)d_in[0];
    const float* Wq = (const float*)d_in[1];
    const float* Wk = (const float*)d_in[2];
    const float* Wv = (const float*)d_in[3];
    const float* Wp = (const float*)d_in[4];
    float* out = (float*)d_out;

    float *Qp, *Kp, *Vp, *Op;
    cudaGetSymbolAddress((void**)&Qp, g_Q);
    cudaGetSymbolAddress((void**)&Kp, g_K);
    cudaGetSymbolAddress((void**)&Vp, g_V);
    cudaGetSymbolAddress((void**)&Op, g_O);

    dim3 gg(D_MODEL / 128, MROWS / 128);   // (8, 64)

    sgemm128<<<gg, 256>>>(x, Wq, Qp, MROWS, D_MODEL, D_MODEL);
    sgemm128<<<gg, 256>>>(x, Wk, Kp, MROWS, D_MODEL, D_MODEL);
    sgemm128<<<gg, 256>>>(x, Wv, Vp, MROWS, D_MODEL, D_MODEL);

    cudaFuncSetAttribute(attn64, cudaFuncAttributeMaxDynamicSharedMemorySize,
                         (int)ATT_SMEM);
    attn64<<<dim3(SEQ / 64, HEADS, BATCH), 256, ATT_SMEM>>>(Qp, Kp, Vp, Op);

    sgemm128<<<gg, 256>>>(Op, Wp, out, MROWS, D_MODEL, D_MODEL);
}

// round 3
// speedup vs baseline: 1.6662x; 1.6662x over previous
#include <cuda_runtime.h>
#include <math.h>

#define D_MODEL 1024
#define HEADS   16
#define DH      64
#define SEQ     1024
#define BATCH   8
#define MROWS   (BATCH*SEQ)   // 8192

// ---- scratch (no cudaMalloc allowed) ----
__device__ float g_Q[MROWS*D_MODEL];
__device__ float g_K[MROWS*D_MODEL];
__device__ float g_V[MROWS*D_MODEL];
__device__ float g_O[MROWS*D_MODEL];

// ============================================================
// SGEMM: C[M,N] = A[M,K] @ B[K,N], all row-major fp32.
// 128x128 tile, BK=16, 256 threads, 8x8 micro-tile per thread.
// (measured at SIMT fp32 roofline — unchanged this round)
// ============================================================
__global__ __launch_bounds__(256) void sgemm128(
    const float* __restrict__ A, const float* __restrict__ B,
    float* __restrict__ C, int M, int N, int K)
{
    __shared__ float As[16][132];   // [k][m], padded
    __shared__ float Bs[16][128];   // [k][n]

    const int tid = threadIdx.x;
    const int m0 = blockIdx.y << 7;
    const int n0 = blockIdx.x << 7;
    const int ty = tid >> 4;        // 0..15
    const int tx = tid & 15;        // 0..15

    float acc[8][8];
    #pragma unroll
    for (int i = 0; i < 8; i++)
        #pragma unroll
        for (int j = 0; j < 8; j++) acc[i][j] = 0.f;

    for (int k0 = 0; k0 < K; k0 += 16) {
        #pragma unroll
        for (int t = 0; t < 2; t++) {
            int f = tid + (t << 8);
            int ar = f >> 2, ac = (f & 3) << 2;
            float4 a4 = *(const float4*)&A[(m0 + ar) * K + k0 + ac];
            As[ac + 0][ar] = a4.x;
            As[ac + 1][ar] = a4.y;
            As[ac + 2][ar] = a4.z;
            As[ac + 3][ar] = a4.w;
            int br = f >> 5, bc = (f & 31) << 2;
            *(float4*)&Bs[br][bc] = *(const float4*)&B[(k0 + br) * N + n0 + bc];
        }
        __syncthreads();

        #pragma unroll
        for (int kk = 0; kk < 16; kk++) {
            float a[8], b[8];
            *(float4*)(a)     = *(float4*)&As[kk][ty * 8];
            *(float4*)(a + 4) = *(float4*)&As[kk][ty * 8 + 4];
            *(float4*)(b)     = *(float4*)&Bs[kk][tx * 8];
            *(float4*)(b + 4) = *(float4*)&Bs[kk][tx * 8 + 4];
            #pragma unroll
            for (int i = 0; i < 8; i++)
                #pragma unroll
                for (int j = 0; j < 8; j++)
                    acc[i][j] = fmaf(a[i], b[j], acc[i][j]);
        }
        __syncthreads();
    }

    #pragma unroll
    for (int i = 0; i < 8; i++) {
        float* cp = &C[(m0 + ty * 8 + i) * N + n0 + tx * 8];
        *(float4*)(cp)     = make_float4(acc[i][0], acc[i][1], acc[i][2], acc[i][3]);
        *(float4*)(cp + 4) = make_float4(acc[i][4], acc[i][5], acc[i][6], acc[i][7]);
    }
}

// ============================================================
// Flash attention v2: CTA = 128 queries x (head, batch).
// Key blocks of 64. 256 threads, 8x4 micro-tiles for both
// S = (Q/8)K^T and O += P V. Softmax fully in registers
// (16-lane shuffle row reductions). P goes to smem transposed
// exactly once per key block.
//
// Thread map: rowg = tid>>4 (rows rowg*8..+8 of 128)
//             colg = tid&15 (cols colg*4..+4 of 64)
// Lanes 0-15 / 16-31 of a warp share rowg -> shfl_xor 1,2,4,8
// reduce within a row group.
// ============================================================
#define QPAD 132
#define KPAD 68
#define VPAD 68
#define PPAD 132
#define ATT_SMEM ((64*QPAD + 64*KPAD + 64*VPAD + 64*PPAD) * sizeof(float))  // 100 KB

__global__ __launch_bounds__(256, 2) void attn128(
    const float* __restrict__ Q, const float* __restrict__ K,
    const float* __restrict__ V, float* __restrict__ O)
{
    extern __shared__ float sm[];
    float* Qd = sm;                    // [d][i]  64 x QPAD (prescaled by 1/8)
    float* Kd = Qd + 64 * QPAD;        // [d][j]  64 x KPAD
    float* Vs = Kd + 64 * KPAD;        // [j][c]  64 x VPAD
    float* Ps = Vs + 64 * VPAD;        // [j][i]  64 x PPAD (P transposed)

    const int tid = threadIdx.x;
    const int qb = blockIdx.x;         // 0..7  (128 queries each)
    const int h  = blockIdx.y;         // 0..15
    const int b  = blockIdx.z;         // 0..7
    const int base = (b * SEQ) * D_MODEL + h * DH;

    const int rowg = tid >> 4;         // 0..15
    const int colg = tid & 15;         // 0..15

    // ---- load Q tile (128 x 64) transposed into Qd[d][i], fold 1/8 ----
    #pragma unroll
    for (int t = 0; t < 8; t++) {
        int f = tid + (t << 8);
        int i = f >> 4, d4 = (f & 15) << 2;
        float4 q = *(const float4*)&Q[base + (qb * 128 + i) * D_MODEL + d4];
        Qd[(d4 + 0) * QPAD + i] = q.x * 0.125f;
        Qd[(d4 + 1) * QPAD + i] = q.y * 0.125f;
        Qd[(d4 + 2) * QPAD + i] = q.z * 0.125f;
        Qd[(d4 + 3) * QPAD + i] = q.w * 0.125f;
    }

    float o[32];
    float m[8], l[8];
    #pragma unroll
    for (int i = 0; i < 32; i++) o[i] = 0.f;
    #pragma unroll
    for (int u = 0; u < 8; u++) { m[u] = -1e30f; l[u] = 0.f; }

    for (int kb = 0; kb < SEQ / 64; kb++) {
        __syncthreads();   // prior iter's Kd/Vs/Ps reads complete
        // ---- load K tile transposed [d][j], V tile natural [j][c] ----
        #pragma unroll
        for (int t = 0; t < 4; t++) {
            int f = tid + (t << 8);
            int j = f >> 4, d4 = (f & 15) << 2;
            float4 kv = *(const float4*)&K[base + (kb * 64 + j) * D_MODEL + d4];
            Kd[(d4 + 0) * KPAD + j] = kv.x;
            Kd[(d4 + 1) * KPAD + j] = kv.y;
            Kd[(d4 + 2) * KPAD + j] = kv.z;
            Kd[(d4 + 3) * KPAD + j] = kv.w;
            *(float4*)&Vs[j * VPAD + d4] =
                *(const float4*)&V[base + (kb * 64 + j) * D_MODEL + d4];
        }
        __syncthreads();

        // ---- Phase A: S fragment (8 rows x 4 keys) = (Q/8) @ K^T ----
        float acc[8][4];
        #pragma unroll
        for (int u = 0; u < 8; u++)
            #pragma unroll
            for (int v = 0; v < 4; v++) acc[u][v] = 0.f;

        #pragma unroll
        for (int d = 0; d < 64; d++) {
            float qa[8];
            *(float4*)(qa)     = *(float4*)&Qd[d * QPAD + rowg * 8];
            *(float4*)(qa + 4) = *(float4*)&Qd[d * QPAD + rowg * 8 + 4];
            float4 k4 = *(float4*)&Kd[d * KPAD + colg * 4];
            float ka[4] = {k4.x, k4.y, k4.z, k4.w};
            #pragma unroll
            for (int u = 0; u < 8; u++)
                #pragma unroll
                for (int v = 0; v < 4; v++)
                    acc[u][v] = fmaf(qa[u], ka[v], acc[u][v]);
        }

        // ---- Phase B: online softmax in registers ----
        #pragma unroll
        for (int u = 0; u < 8; u++) {
            float mx = fmaxf(fmaxf(acc[u][0], acc[u][1]),
                             fmaxf(acc[u][2], acc[u][3]));
            mx = fmaxf(mx, __shfl_xor_sync(0xffffffffu, mx, 1));
            mx = fmaxf(mx, __shfl_xor_sync(0xffffffffu, mx, 2));
            mx = fmaxf(mx, __shfl_xor_sync(0xffffffffu, mx, 4));
            mx = fmaxf(mx, __shfl_xor_sync(0xffffffffu, mx, 8));
            float m_new = fmaxf(m[u], mx);
            float alpha = __expf(m[u] - m_new);
            m[u] = m_new;
            float ls = 0.f;
            #pragma unroll
            for (int v = 0; v < 4; v++) {
                acc[u][v] = __expf(acc[u][v] - m_new);
                ls += acc[u][v];
            }
            ls += __shfl_xor_sync(0xffffffffu, ls, 1);
            ls += __shfl_xor_sync(0xffffffffu, ls, 2);
            ls += __shfl_xor_sync(0xffffffffu, ls, 4);
            ls += __shfl_xor_sync(0xffffffffu, ls, 8);
            l[u] = l[u] * alpha + ls;
            o[u * 4 + 0] *= alpha;
            o[u * 4 + 1] *= alpha;
            o[u * 4 + 2] *= alpha;
            o[u * 4 + 3] *= alpha;
        }

        // ---- write P transposed: Ps[j][i] ----
        #pragma unroll
        for (int v = 0; v < 4; v++) {
            float* pr = &Ps[(colg * 4 + v) * PPAD + rowg * 8];
            *(float4*)(pr)     = make_float4(acc[0][v], acc[1][v], acc[2][v], acc[3][v]);
            *(float4*)(pr + 4) = make_float4(acc[4][v], acc[5][v], acc[6][v], acc[7][v]);
        }
        __syncthreads();

        // ---- Phase C: O += P @ V (8x4 micro, contraction over j) ----
        #pragma unroll
        for (int j = 0; j < 64; j++) {
            float pa[8];
            *(float4*)(pa)     = *(float4*)&Ps[j * PPAD + rowg * 8];
            *(float4*)(pa + 4) = *(float4*)&Ps[j * PPAD + rowg * 8 + 4];
            float4 vv = *(float4*)&Vs[j * VPAD + colg * 4];
            float va[4] = {vv.x, vv.y, vv.z, vv.w};
            #pragma unroll
            for (int u = 0; u < 8; u++)
                #pragma unroll
                for (int v = 0; v < 4; v++)
                    o[u * 4 + v] = fmaf(pa[u], va[v], o[u * 4 + v]);
        }
    }

    // ---- epilogue ----
    #pragma unroll
    for (int u = 0; u < 8; u++) {
        float inv = 1.f / l[u];
        float* op = &O[base + (qb * 128 + rowg * 8 + u) * D_MODEL + colg * 4];
        *(float4*)op = make_float4(o[u * 4 + 0] * inv, o[u * 4 + 1] * inv,
                                   o[u * 4 + 2] * inv, o[u * 4 + 3] * inv);
    }
}

// ============================================================
extern "C" void kernel_launch(void* const* d_in, const int* in_sizes, int n_in,
                              void* d_out, int out_size)
{
    const float* x  = (const float*)d_in[0];
    const float* Wq = (const float*)d_in[1];
    const float* Wk = (const float*)d_in[2];
    const float* Wv = (const float*)d_in[3];
    const float* Wp = (const float*)d_in[4];
    float* out = (float*)d_out;

    float *Qp, *Kp, *Vp, *Op;
    cudaGetSymbolAddress((void**)&Qp, g_Q);
    cudaGetSymbolAddress((void**)&Kp, g_K);
    cudaGetSymbolAddress((void**)&Vp, g_V);
    cudaGetSymbolAddress((void**)&Op, g_O);

    dim3 gg(D_MODEL / 128, MROWS / 128);   // (8, 64)

    sgemm128<<<gg, 256>>>(x, Wq, Qp, MROWS, D_MODEL, D_MODEL);
    sgemm128<<<gg, 256>>>(x, Wk, Kp, MROWS, D_MODEL, D_MODEL);
    sgemm128<<<gg, 256>>>(x, Wv, Vp, MROWS, D_MODEL, D_MODEL);

    static int cfg_done = 0;
    if (!cfg_done) {
        cudaFuncSetAttribute(attn128, cudaFuncAttributeMaxDynamicSharedMemorySize,
                             (int)ATT_SMEM);
        cfg_done = 1;
    }
    attn128<<<dim3(SEQ / 128, HEADS, BATCH), 256, ATT_SMEM>>>(Qp, Kp, Vp, Op);

    sgemm128<<<gg, 256>>>(Op, Wp, out, MROWS, D_MODEL, D_MODEL);
}

// round 5
// speedup vs baseline: 2.7851x; 1.6715x over previous
#include <cuda_runtime.h>
#include <cuda_bf16.h>
#include <math.h>
#include <cstdint>

#define D_MODEL 1024
#define HEADS   16
#define DH      64
#define SEQ     1024
#define BATCH   8
#define MROWS   (BATCH*SEQ)   // 8192

// ---- scratch (no cudaMalloc allowed) ----
__device__ float         g_Q [MROWS*D_MODEL];
__device__ float         g_K [MROWS*D_MODEL];
__device__ float         g_V [MROWS*D_MODEL];
__device__ __nv_bfloat16 g_xh[MROWS*D_MODEL];
__device__ __nv_bfloat16 g_xl[MROWS*D_MODEL];
__device__ __nv_bfloat16 g_Oh[MROWS*D_MODEL];
__device__ __nv_bfloat16 g_Ol[MROWS*D_MODEL];
__device__ __nv_bfloat16 g_Wh[4][D_MODEL*D_MODEL];  // natural [k][n]
__device__ __nv_bfloat16 g_Wl[4][D_MODEL*D_MODEL];

// ============================================================
// PTX helpers — only sm_80-era instructions (harness PTX target
// is plain sm_103; tcgen05 is unavailable there).
// ============================================================
__device__ __forceinline__ uint32_t smem_u32(const void* p) {
    uint32_t a;
    asm("{ .reg .u64 t; cvta.to.shared.u64 t, %1; cvt.u32.u64 %0, t; }"
        : "=r"(a) : "l"(p));
    return a;
}
__device__ __forceinline__ void cpa16(uint32_t dst, const void* src) {
    asm volatile("cp.async.cg.shared.global [%0], [%1], 16;"
                 :: "r"(dst), "l"(src) : "memory");
}
#define CP_COMMIT() asm volatile("cp.async.commit_group;" ::: "memory")
#define CP_WAIT1()  asm volatile("cp.async.wait_group 1;" ::: "memory")
#define CP_WAIT0()  asm volatile("cp.async.wait_group 0;" ::: "memory")

__device__ __forceinline__ void ldsm_x4(uint32_t* r, uint32_t addr) {
    asm volatile("ldmatrix.sync.aligned.m8n8.x4.shared.b16 {%0,%1,%2,%3}, [%4];"
                 : "=r"(r[0]), "=r"(r[1]), "=r"(r[2]), "=r"(r[3]) : "r"(addr));
}
__device__ __forceinline__ void ldsm_x4t(uint32_t* r, uint32_t addr) {
    asm volatile("ldmatrix.sync.aligned.m8n8.x4.trans.shared.b16 {%0,%1,%2,%3}, [%4];"
                 : "=r"(r[0]), "=r"(r[1]), "=r"(r[2]), "=r"(r[3]) : "r"(addr));
}
__device__ __forceinline__ void mma16816(float* c, const uint32_t* a,
                                         uint32_t b0, uint32_t b1) {
    asm volatile(
        "mma.sync.aligned.m16n8k16.row.col.f32.bf16.bf16.f32 "
        "{%0,%1,%2,%3}, {%4,%5,%6,%7}, {%8,%9}, {%0,%1,%2,%3};"
        : "+f"(c[0]), "+f"(c[1]), "+f"(c[2]), "+f"(c[3])
        : "r"(a[0]), "r"(a[1]), "r"(a[2]), "r"(a[3]), "r"(b0), "r"(b1));
}

// ============================================================
// split conversion (elementwise; also used for W — no transpose
// needed since hgemm3 consumes B as [k][n])
// ============================================================
__global__ void fsplit(const float* __restrict__ X,
                       __nv_bfloat16* __restrict__ Xh,
                       __nv_bfloat16* __restrict__ Xl) {
    int i = (blockIdx.x * blockDim.x + threadIdx.x) * 4;
    float4 v = *(const float4*)&X[i];
    float a[4] = {v.x, v.y, v.z, v.w};
    __nv_bfloat16 h[4], l[4];
    #pragma unroll
    for (int j = 0; j < 4; j++) {
        h[j] = __float2bfloat16_rn(a[j]);
        l[j] = __float2bfloat16_rn(a[j] - __bfloat162float(h[j]));
    }
    *(__nv_bfloat162*)&Xh[i]     = __halves2bfloat162(h[0], h[1]);
    *(__nv_bfloat162*)&Xh[i + 2] = __halves2bfloat162(h[2], h[3]);
    *(__nv_bfloat162*)&Xl[i]     = __halves2bfloat162(l[0], l[1]);
    *(__nv_bfloat162*)&Xl[i + 2] = __halves2bfloat162(l[2], l[3]);
}

// ============================================================
// hgemm3: C[M,1024] fp32 = A @ W via bf16 3-split on mma.sync.
//   Ah/Al: [M,1024] bf16 row-major; Bh/Bl: [1024,1024] bf16 [k][n].
//   CTA: 128x128 tile, 8 warps (2m x 4n), warp tile 64x32.
//   BK=64, cp.async double-buffered. Effective K = 3*1024.
// ============================================================
#define AST_B 144                      // A smem row stride bytes (72 bf16)
#define BST_B 272                      // B smem row stride bytes (136 bf16)
#define ABYTES (128 * AST_B)           // 18432
#define BBYTES (64 * BST_B)            // 17408
#define STAGE_B (ABYTES + BBYTES)      // 35840
#define GEM_SMEM (2 * STAGE_B)         // 71680

__device__ __forceinline__ void gload(uint32_t aT, uint32_t bT,
    const __nv_bfloat16* __restrict__ Ap, const __nv_bfloat16* __restrict__ Bp,
    int m0, int n0, int kk0, int tid)
{
    #pragma unroll
    for (int t = 0; t < 4; t++) {          // A: 128 rows x 64 (8x16B chunks)
        int idx = tid + (t << 8);
        int r = idx >> 3, c = idx & 7;
        cpa16(aT + r * AST_B + c * 16,
              Ap + (size_t)(m0 + r) * D_MODEL + kk0 + c * 8);
    }
    #pragma unroll
    for (int t = 0; t < 4; t++) {          // B: 64 rows x 128 (16x16B chunks)
        int idx = tid + (t << 8);
        int r = idx >> 4, c = idx & 15;
        cpa16(bT + r * BST_B + c * 16,
              Bp + (size_t)(kk0 + r) * D_MODEL + n0 + c * 8);
    }
}

__global__ __launch_bounds__(256, 2) void hgemm3(
    const __nv_bfloat16* __restrict__ Ah, const __nv_bfloat16* __restrict__ Al,
    const __nv_bfloat16* __restrict__ Bh, const __nv_bfloat16* __restrict__ Bl,
    float* __restrict__ C)
{
    extern __shared__ char dsm[];
    const uint32_t sb = smem_u32(dsm);

    const int tid = threadIdx.x;
    const int wid = tid >> 5;
    const int lane = tid & 31;
    const int wm = wid >> 2;            // 0..1  (m offset 64*wm)
    const int wn = wid & 3;             // 0..3  (n offset 32*wn)
    const int m0 = blockIdx.y << 7;
    const int n0 = blockIdx.x << 7;
    const int lr = lane & 15, lc = lane >> 4;   // ldmatrix addressing

    const __nv_bfloat16* Asel[3] = {Ah, Ah, Al};
    const __nv_bfloat16* Bsel[3] = {Bh, Bl, Bh};

    float acc[16][4];
    #pragma unroll
    for (int i = 0; i < 16; i++)
        #pragma unroll
        for (int j = 0; j < 4; j++) acc[i][j] = 0.f;

    gload(sb, sb + ABYTES, Asel[0], Bsel[0], m0, n0, 0, tid);
    CP_COMMIT();

    #pragma unroll 1
    for (int s = 0; s < 48; s++) {
        if (s < 47) {
            int s1 = s + 1, p = s1 >> 4;
            uint32_t base = sb + (s1 & 1) * STAGE_B;
            gload(base, base + ABYTES, Asel[p], Bsel[p], m0, n0,
                  (s1 & 15) << 6, tid);
            CP_COMMIT();
            CP_WAIT1();
        } else {
            CP_WAIT0();
        }
        __syncthreads();

        const uint32_t aT = sb + (s & 1) * STAGE_B;
        const uint32_t bT = aT + ABYTES;
        #pragma unroll
        for (int k16 = 0; k16 < 4; k16++) {
            uint32_t a[4][4], b[2][4];
            #pragma unroll
            for (int mt = 0; mt < 4; mt++)
                ldsm_x4(a[mt], aT + (wm * 64 + mt * 16 + lr) * AST_B
                               + k16 * 32 + lc * 16);
            #pragma unroll
            for (int nt2 = 0; nt2 < 2; nt2++)
                ldsm_x4t(b[nt2], bT + (k16 * 16 + lr) * BST_B
                                + wn * 64 + nt2 * 32 + lc * 16);
            #pragma unroll
            for (int mt = 0; mt < 4; mt++)
                #pragma unroll
                for (int nt = 0; nt < 4; nt++)
                    mma16816(acc[mt * 4 + nt], a[mt],
                             b[nt >> 1][(nt & 1) * 2],
                             b[nt >> 1][(nt & 1) * 2 + 1]);
        }
        __syncthreads();
    }

    // epilogue: c0=C[g][2tg], c1=C[g][2tg+1], c2=C[g+8][2tg], c3=C[g+8][2tg+1]
    const int g = lane >> 2, tg = lane & 3;
    #pragma unroll
    for (int mt = 0; mt < 4; mt++) {
        int row = m0 + wm * 64 + mt * 16 + g;
        #pragma unroll
        for (int nt = 0; nt < 4; nt++) {
            float* cp = &C[(size_t)row * D_MODEL + n0 + wn * 32 + nt * 8 + tg * 2];
            *(float2*)cp = make_float2(acc[mt * 4 + nt][0], acc[mt * 4 + nt][1]);
            *(float2*)(cp + 8 * D_MODEL) =
                make_float2(acc[mt * 4 + nt][2], acc[mt * 4 + nt][3]);
        }
    }
}

// ============================================================
// Flash attention (R3 structure), epilogue emits bf16 hi/lo of O.
// ============================================================
#define QPAD 132
#define KPAD 68
#define VPAD 68
#define PPAD 132
#define ATT_SMEM ((64*QPAD + 64*KPAD + 64*VPAD + 64*PPAD) * sizeof(float))

__global__ __launch_bounds__(256, 2) void attn128(
    const float* __restrict__ Q, const float* __restrict__ K,
    const float* __restrict__ V,
    __nv_bfloat16* __restrict__ Oh, __nv_bfloat16* __restrict__ Ol)
{
    extern __shared__ float sm[];
    float* Qd = sm;
    float* Kd = Qd + 64 * QPAD;
    float* Vs = Kd + 64 * KPAD;
    float* Ps = Vs + 64 * VPAD;

    const int tid = threadIdx.x;
    const int qb = blockIdx.x;
    const int h  = blockIdx.y;
    const int b  = blockIdx.z;
    const int base = (b * SEQ) * D_MODEL + h * DH;

    const int rowg = tid >> 4;
    const int colg = tid & 15;

    #pragma unroll
    for (int t = 0; t < 8; t++) {
        int f = tid + (t << 8);
        int i = f >> 4, d4 = (f & 15) << 2;
        float4 q = *(const float4*)&Q[base + (qb * 128 + i) * D_MODEL + d4];
        Qd[(d4 + 0) * QPAD + i] = q.x * 0.125f;
        Qd[(d4 + 1) * QPAD + i] = q.y * 0.125f;
        Qd[(d4 + 2) * QPAD + i] = q.z * 0.125f;
        Qd[(d4 + 3) * QPAD + i] = q.w * 0.125f;
    }

    float o[32];
    float m[8], l[8];
    #pragma unroll
    for (int i = 0; i < 32; i++) o[i] = 0.f;
    #pragma unroll
    for (int u = 0; u < 8; u++) { m[u] = -1e30f; l[u] = 0.f; }

    for (int kb = 0; kb < SEQ / 64; kb++) {
        __syncthreads();
        #pragma unroll
        for (int t = 0; t < 4; t++) {
            int f = tid + (t << 8);
            int j = f >> 4, d4 = (f & 15) << 2;
            float4 kv = *(const float4*)&K[base + (kb * 64 + j) * D_MODEL + d4];
            Kd[(d4 + 0) * KPAD + j] = kv.x;
            Kd[(d4 + 1) * KPAD + j] = kv.y;
            Kd[(d4 + 2) * KPAD + j] = kv.z;
            Kd[(d4 + 3) * KPAD + j] = kv.w;
            *(float4*)&Vs[j * VPAD + d4] =
                *(const float4*)&V[base + (kb * 64 + j) * D_MODEL + d4];
        }
        __syncthreads();

        float acc[8][4];
        #pragma unroll
        for (int u = 0; u < 8; u++)
            #pragma unroll
            for (int v = 0; v < 4; v++) acc[u][v] = 0.f;

        #pragma unroll
        for (int d = 0; d < 64; d++) {
            float qa[8];
            *(float4*)(qa)     = *(float4*)&Qd[d * QPAD + rowg * 8];
            *(float4*)(qa + 4) = *(float4*)&Qd[d * QPAD + rowg * 8 + 4];
            float4 k4 = *(float4*)&Kd[d * KPAD + colg * 4];
            float ka[4] = {k4.x, k4.y, k4.z, k4.w};
            #pragma unroll
            for (int u = 0; u < 8; u++)
                #pragma unroll
                for (int v = 0; v < 4; v++)
                    acc[u][v] = fmaf(qa[u], ka[v], acc[u][v]);
        }

        #pragma unroll
        for (int u = 0; u < 8; u++) {
            float mx = fmaxf(fmaxf(acc[u][0], acc[u][1]),
                             fmaxf(acc[u][2], acc[u][3]));
            mx = fmaxf(mx, __shfl_xor_sync(0xffffffffu, mx, 1));
            mx = fmaxf(mx, __shfl_xor_sync(0xffffffffu, mx, 2));
            mx = fmaxf(mx, __shfl_xor_sync(0xffffffffu, mx, 4));
            mx = fmaxf(mx, __shfl_xor_sync(0xffffffffu, mx, 8));
            float m_new = fmaxf(m[u], mx);
            float alpha = __expf(m[u] - m_new);
            m[u] = m_new;
            float ls = 0.f;
            #pragma unroll
            for (int v = 0; v < 4; v++) {
                acc[u][v] = __expf(acc[u][v] - m_new);
                ls += acc[u][v];
            }
            ls += __shfl_xor_sync(0xffffffffu, ls, 1);
            ls += __shfl_xor_sync(0xffffffffu, ls, 2);
            ls += __shfl_xor_sync(0xffffffffu, ls, 4);
            ls += __shfl_xor_sync(0xffffffffu, ls, 8);
            l[u] = l[u] * alpha + ls;
            o[u * 4 + 0] *= alpha;
            o[u * 4 + 1] *= alpha;
            o[u * 4 + 2] *= alpha;
            o[u * 4 + 3] *= alpha;
        }

        #pragma unroll
        for (int v = 0; v < 4; v++) {
            float* pr = &Ps[(colg * 4 + v) * PPAD + rowg * 8];
            *(float4*)(pr)     = make_float4(acc[0][v], acc[1][v], acc[2][v], acc[3][v]);
            *(float4*)(pr + 4) = make_float4(acc[4][v], acc[5][v], acc[6][v], acc[7][v]);
        }
        __syncthreads();

        #pragma unroll
        for (int j = 0; j < 64; j++) {
            float pa[8];
            *(float4*)(pa)     = *(float4*)&Ps[j * PPAD + rowg * 8];
            *(float4*)(pa + 4) = *(float4*)&Ps[j * PPAD + rowg * 8 + 4];
            float4 vv = *(float4*)&Vs[j * VPAD + colg * 4];
            float va[4] = {vv.x, vv.y, vv.z, vv.w};
            #pragma unroll
            for (int u = 0; u < 8; u++)
                #pragma unroll
                for (int v = 0; v < 4; v++)
                    o[u * 4 + v] = fmaf(pa[u], va[v], o[u * 4 + v]);
        }
    }

    #pragma unroll
    for (int u = 0; u < 8; u++) {
        float inv = 1.f / l[u];
        int off = base + (qb * 128 + rowg * 8 + u) * D_MODEL + colg * 4;
        __nv_bfloat16 hh[4], ll[4];
        #pragma unroll
        for (int v = 0; v < 4; v++) {
            float val = o[u * 4 + v] * inv;
            hh[v] = __float2bfloat16_rn(val);
            ll[v] = __float2bfloat16_rn(val - __bfloat162float(hh[v]));
        }
        *(__nv_bfloat162*)&Oh[off]     = __halves2bfloat162(hh[0], hh[1]);
        *(__nv_bfloat162*)&Oh[off + 2] = __halves2bfloat162(hh[2], hh[3]);
        *(__nv_bfloat162*)&Ol[off]     = __halves2bfloat162(ll[0], ll[1]);
        *(__nv_bfloat162*)&Ol[off + 2] = __halves2bfloat162(ll[2], ll[3]);
    }
}

// ============================================================
extern "C" void kernel_launch(void* const* d_in, const int* in_sizes, int n_in,
                              void* d_out, int out_size)
{
    const float* x  = (const float*)d_in[0];
    const float* W[4] = {(const float*)d_in[1], (const float*)d_in[2],
                         (const float*)d_in[3], (const float*)d_in[4]};
    float* out = (float*)d_out;

    float *Qp, *Kp, *Vp;
    __nv_bfloat16 *xh, *xl, *ohp, *olp, *wh[4], *wl[4];
    cudaGetSymbolAddress((void**)&Qp, g_Q);
    cudaGetSymbolAddress((void**)&Kp, g_K);
    cudaGetSymbolAddress((void**)&Vp, g_V);
    cudaGetSymbolAddress((void**)&xh, g_xh);
    cudaGetSymbolAddress((void**)&xl, g_xl);
    cudaGetSymbolAddress((void**)&ohp, g_Oh);
    cudaGetSymbolAddress((void**)&olp, g_Ol);
    {
        __nv_bfloat16 *base_h, *base_l;
        cudaGetSymbolAddress((void**)&base_h, g_Wh);
        cudaGetSymbolAddress((void**)&base_l, g_Wl);
        for (int i = 0; i < 4; i++) {
            wh[i] = base_h + (size_t)i * D_MODEL * D_MODEL;
            wl[i] = base_l + (size_t)i * D_MODEL * D_MODEL;
        }
    }

    static int cfg_done = 0;
    if (!cfg_done) {
        cudaFuncSetAttribute(attn128, cudaFuncAttributeMaxDynamicSharedMemorySize,
                             (int)ATT_SMEM);
        cudaFuncSetAttribute(hgemm3, cudaFuncAttributeMaxDynamicSharedMemorySize,
                             GEM_SMEM);
        cfg_done = 1;
    }

    // splits (x and all 4 weights; W stays [k][n])
    fsplit<<<MROWS * D_MODEL / 1024, 256>>>(x, xh, xl);
    for (int i = 0; i < 4; i++)
        fsplit<<<D_MODEL * D_MODEL / 1024, 256>>>(W[i], wh[i], wl[i]);

    dim3 gg(D_MODEL / 128, MROWS / 128);   // (8, 64)
    hgemm3<<<gg, 256, GEM_SMEM>>>(xh, xl, wh[0], wl[0], Qp);
    hgemm3<<<gg, 256, GEM_SMEM>>>(xh, xl, wh[1], wl[1], Kp);
    hgemm3<<<gg, 256, GEM_SMEM>>>(xh, xl, wh[2], wl[2], Vp);

    attn128<<<dim3(SEQ / 128, HEADS, BATCH), 256, ATT_SMEM>>>(Qp, Kp, Vp, ohp, olp);

    hgemm3<<<gg, 256, GEM_SMEM>>>(ohp, olp, wh[3], wl[3], out);
}

// round 6
// speedup vs baseline: 4.0618x; 1.4584x over previous
#include <cuda_runtime.h>
#include <cuda_bf16.h>
#include <math.h>
#include <cstdint>

#define D_MODEL 1024
#define HEADS   16
#define DH      64
#define SEQ     1024
#define BATCH   8
#define MROWS   (BATCH*SEQ)   // 8192

typedef __nv_bfloat16 bf16;

// ---- scratch (no cudaMalloc allowed) ----
__device__ bf16 g_xh[MROWS*D_MODEL];
__device__ bf16 g_xl[MROWS*D_MODEL];
__device__ bf16 g_Qh[MROWS*D_MODEL];
__device__ bf16 g_Ql[MROWS*D_MODEL];
__device__ bf16 g_Kh[MROWS*D_MODEL];
__device__ bf16 g_Kl[MROWS*D_MODEL];
__device__ bf16 g_Vh[MROWS*D_MODEL];
__device__ bf16 g_Vl[MROWS*D_MODEL];
__device__ bf16 g_Oh[MROWS*D_MODEL];
__device__ bf16 g_Ol[MROWS*D_MODEL];
__device__ bf16 g_Wh[4][D_MODEL*D_MODEL];  // natural [k][n]
__device__ bf16 g_Wl[4][D_MODEL*D_MODEL];

// ============================================================
// PTX helpers (sm_80-era only; tcgen05 unavailable at .target sm_103)
// ============================================================
__device__ __forceinline__ uint32_t smem_u32(const void* p) {
    uint32_t a;
    asm("{ .reg .u64 t; cvta.to.shared.u64 t, %1; cvt.u32.u64 %0, t; }"
        : "=r"(a) : "l"(p));
    return a;
}
__device__ __forceinline__ void cpa16(uint32_t dst, const void* src) {
    asm volatile("cp.async.cg.shared.global [%0], [%1], 16;"
                 :: "r"(dst), "l"(src) : "memory");
}
#define CP_COMMIT() asm volatile("cp.async.commit_group;" ::: "memory")
#define CP_WAIT3()  asm volatile("cp.async.wait_group 3;" ::: "memory")
#define CP_WAIT1()  asm volatile("cp.async.wait_group 1;" ::: "memory")

__device__ __forceinline__ void ldsm_x4(uint32_t* r, uint32_t addr) {
    asm volatile("ldmatrix.sync.aligned.m8n8.x4.shared.b16 {%0,%1,%2,%3}, [%4];"
                 : "=r"(r[0]), "=r"(r[1]), "=r"(r[2]), "=r"(r[3]) : "r"(addr));
}
__device__ __forceinline__ void ldsm_x4t(uint32_t* r, uint32_t addr) {
    asm volatile("ldmatrix.sync.aligned.m8n8.x4.trans.shared.b16 {%0,%1,%2,%3}, [%4];"
                 : "=r"(r[0]), "=r"(r[1]), "=r"(r[2]), "=r"(r[3]) : "r"(addr));
}
__device__ __forceinline__ void mma16816(float* c, const uint32_t* a,
                                         uint32_t b0, uint32_t b1) {
    asm volatile(
        "mma.sync.aligned.m16n8k16.row.col.f32.bf16.bf16.f32 "
        "{%0,%1,%2,%3}, {%4,%5,%6,%7}, {%8,%9}, {%0,%1,%2,%3};"
        : "+f"(c[0]), "+f"(c[1]), "+f"(c[2]), "+f"(c[3])
        : "r"(a[0]), "r"(a[1]), "r"(a[2]), "r"(a[3]), "r"(b0), "r"(b1));
}
__device__ __forceinline__ float ex2f(float x) {
    float r; asm("ex2.approx.f32 %0, %1;" : "=f"(r) : "f"(x)); return r;
}
__device__ __forceinline__ uint32_t pk2(float lo, float hi) {   // bf16x2 {lo,hi}
    uint32_t d;
    asm("cvt.rn.bf16x2.f32 %0, %1, %2;" : "=r"(d) : "f"(hi), "f"(lo));
    return d;
}
__device__ __forceinline__ float2 upk2(uint32_t v) {
    __nv_bfloat162 t = *reinterpret_cast<__nv_bfloat162*>(&v);
    return __bfloat1622float2(t);
}

// ============================================================
// fsplit: fp32 -> bf16 hi/lo (x and W, elementwise)
// ============================================================
__global__ void fsplit(const float* __restrict__ X,
                       bf16* __restrict__ Xh, bf16* __restrict__ Xl) {
    int i = (blockIdx.x * blockDim.x + threadIdx.x) * 4;
    float4 v = *(const float4*)&X[i];
    float a[4] = {v.x, v.y, v.z, v.w};
    bf16 h[4], l[4];
    #pragma unroll
    for (int j = 0; j < 4; j++) {
        h[j] = __float2bfloat16_rn(a[j]);
        l[j] = __float2bfloat16_rn(a[j] - __bfloat162float(h[j]));
    }
    *(__nv_bfloat162*)&Xh[i]     = __halves2bfloat162(h[0], h[1]);
    *(__nv_bfloat162*)&Xh[i + 2] = __halves2bfloat162(h[2], h[3]);
    *(__nv_bfloat162*)&Xl[i]     = __halves2bfloat162(l[0], l[1]);
    *(__nv_bfloat162*)&Xl[i + 2] = __halves2bfloat162(l[2], l[3]);
}

// ============================================================
// hgemm3t: C[M,1024] = A @ W via bf16 3-split on mma.sync.
//   CTA 256x128, 8 warps (4m x 2n) of 64x64, BK=64, 4-stage cp.async.
//   MODE 0: write fp32 C.  MODE 1: write bf16 hi/lo (Ch,Cl), scaled.
// ============================================================
#define AST 144                         // A smem row stride (72 bf16)
#define BST 272                         // B smem row stride (136 bf16)
#define ABYT (256 * AST)                // 36864
#define BBYT (64 * BST)                 // 17408
#define STG  (ABYT + BBYT)              // 54272
#define GEM_SMEM (4 * STG)              // 217088

__device__ __forceinline__ void gload(uint32_t st,
    const bf16* __restrict__ Ap, const bf16* __restrict__ Bp,
    int m0, int n0, int kk0, int tid)
{
    #pragma unroll
    for (int t = 0; t < 8; t++) {            // A: 256x64 = 2048 16B chunks
        int idx = tid + (t << 8);
        int r = idx >> 3, c = idx & 7;
        cpa16(st + r * AST + c * 16,
              Ap + (size_t)(m0 + r) * D_MODEL + kk0 + c * 8);
    }
    #pragma unroll
    for (int t = 0; t < 4; t++) {            // B: 64x128 = 1024 chunks
        int idx = tid + (t << 8);
        int r = idx >> 4, c = idx & 15;
        cpa16(st + ABYT + r * BST + c * 16,
              Bp + (size_t)(kk0 + r) * D_MODEL + n0 + c * 8);
    }
}

template<int MODE>
__global__ __launch_bounds__(256) void hgemm3t(
    const bf16* __restrict__ Ah, const bf16* __restrict__ Al,
    const bf16* __restrict__ Bh, const bf16* __restrict__ Bl,
    float* __restrict__ C, bf16* __restrict__ Ch, bf16* __restrict__ Cl,
    float scale)
{
    extern __shared__ char dsm[];
    const uint32_t sb = smem_u32(dsm);

    const int tid = threadIdx.x;
    const int wid = tid >> 5;
    const int lane = tid & 31;
    const int wm = wid >> 1, wn = wid & 1;
    const int lr = lane & 15, lc = lane >> 4;
    const int m0 = blockIdx.y << 8;
    const int n0 = blockIdx.x << 7;

    const bf16* Asel[3] = {Ah, Ah, Al};
    const bf16* Bsel[3] = {Bh, Bl, Bh};

    float acc[32][4];
    #pragma unroll
    for (int i = 0; i < 32; i++)
        #pragma unroll
        for (int j = 0; j < 4; j++) acc[i][j] = 0.f;

    #pragma unroll
    for (int p = 0; p < 3; p++) {
        gload(sb + p * STG, Asel[p >> 4], Bsel[p >> 4], m0, n0, (p & 15) << 6, tid);
        CP_COMMIT();
    }

    #pragma unroll 1
    for (int s = 0; s < 48; s++) {
        if (s + 3 < 48) {
            int c = s + 3, p = c >> 4;
            gload(sb + (c & 3) * STG, Asel[p], Bsel[p], m0, n0, (c & 15) << 6, tid);
        }
        CP_COMMIT();
        CP_WAIT3();
        __syncthreads();

        const uint32_t aT = sb + (s & 3) * STG;
        const uint32_t bT = aT + ABYT;
        #pragma unroll
        for (int k16 = 0; k16 < 4; k16++) {
            uint32_t a[4][4], b[4][4];
            #pragma unroll
            for (int mt = 0; mt < 4; mt++)
                ldsm_x4(a[mt], aT + (wm * 64 + mt * 16 + lr) * AST
                               + k16 * 32 + lc * 16);
            #pragma unroll
            for (int cg = 0; cg < 4; cg++)
                ldsm_x4t(b[cg], bT + (k16 * 16 + lr) * BST
                                + wn * 128 + cg * 32 + lc * 16);
            #pragma unroll
            for (int mt = 0; mt < 4; mt++)
                #pragma unroll
                for (int nt = 0; nt < 8; nt++)
                    mma16816(acc[mt * 8 + nt], a[mt],
                             b[nt >> 1][(nt & 1) * 2],
                             b[nt >> 1][(nt & 1) * 2 + 1]);
        }
        __syncthreads();
    }

    const int g = lane >> 2, tg = lane & 3;
    #pragma unroll
    for (int mt = 0; mt < 4; mt++) {
        int row = m0 + wm * 64 + mt * 16 + g;
        #pragma unroll
        for (int nt = 0; nt < 8; nt++) {
            int col = n0 + wn * 64 + nt * 8 + tg * 2;
            float* ac = acc[mt * 8 + nt];
            if (MODE == 0) {
                float* cp = &C[(size_t)row * D_MODEL + col];
                *(float2*)cp = make_float2(ac[0], ac[1]);
                *(float2*)(cp + 8 * D_MODEL) = make_float2(ac[2], ac[3]);
            } else {
                float v0 = ac[0] * scale, v1 = ac[1] * scale;
                float v2 = ac[2] * scale, v3 = ac[3] * scale;
                uint32_t h01 = pk2(v0, v1), h23 = pk2(v2, v3);
                float2 f01 = upk2(h01), f23 = upk2(h23);
                size_t o0 = (size_t)row * D_MODEL + col;
                size_t o1 = o0 + 8 * D_MODEL;
                *(uint32_t*)&Ch[o0] = h01;
                *(uint32_t*)&Ch[o1] = h23;
                *(uint32_t*)&Cl[o0] = pk2(v0 - f01.x, v1 - f01.y);
                *(uint32_t*)&Cl[o1] = pk2(v2 - f23.x, v3 - f23.y);
            }
        }
    }
}

// ============================================================
// attn_mma: flash attention on mma.sync, bf16 3-split both GEMMs.
//   CTA = 128 queries x (head, batch). 8 warps, warp = 16 q-rows x 64 keys.
//   Q prescaled by 0.125*log2(e) -> softmax uses ex2 directly.
//   P stays in registers (S fragment == PV A fragment layout).
//   K/V blocks of 64 keys, double-buffered cp.async.
// ============================================================
#define KVB  9216                        // one 64x72 bf16 tile
#define KVST (4 * KVB)                   // Kh,Kl,Vh,Vl per stage = 36864
#define QOFF 0
#define KVOFF (2 * 18432)                // after Qh,Ql
#define ATT_SMEM (KVOFF + 2 * KVST)      // 110592

__device__ __forceinline__ void kvload(uint32_t st,
    const bf16* __restrict__ Kh, const bf16* __restrict__ Kl,
    const bf16* __restrict__ Vh, const bf16* __restrict__ Vl,
    size_t gbase, int tid)
{
    #pragma unroll
    for (int t = 0; t < 2; t++) {        // 64x64 bf16 = 512 chunks per tensor
        int idx = tid + (t << 8);
        int r = idx >> 3, c = idx & 7;
        size_t go = gbase + (size_t)r * D_MODEL + c * 8;
        uint32_t so = r * AST + c * 16;
        cpa16(st + so,           Kh + go);
        cpa16(st + KVB + so,     Kl + go);
        cpa16(st + 2 * KVB + so, Vh + go);
        cpa16(st + 3 * KVB + so, Vl + go);
    }
}

__global__ __launch_bounds__(256, 2) void attn_mma(
    const bf16* __restrict__ Qh, const bf16* __restrict__ Ql,
    const bf16* __restrict__ Kh, const bf16* __restrict__ Kl,
    const bf16* __restrict__ Vh, const bf16* __restrict__ Vl,
    bf16* __restrict__ Oh, bf16* __restrict__ Ol)
{
    extern __shared__ char dsm[];
    const uint32_t sb = smem_u32(dsm);

    const int tid = threadIdx.x;
    const int wid = tid >> 5;
    const int lane = tid & 31;
    const int lr = lane & 15, lc = lane >> 4;
    const int g = lane >> 2, tg = lane & 3;
    const int qb = blockIdx.x, h = blockIdx.y, b = blockIdx.z;
    const size_t qrow0 = (size_t)(b * SEQ + qb * 128);
    const size_t hcol = h * DH;

    // ---- load Q tiles (128x64 each of Qh, Ql) ----
    #pragma unroll
    for (int t = 0; t < 4; t++) {
        int idx = tid + (t << 8);
        int r = idx >> 3, c = idx & 7;
        size_t go = (qrow0 + r) * D_MODEL + hcol + c * 8;
        uint32_t so = r * AST + c * 16;
        cpa16(sb + so, Qh + go);
        cpa16(sb + 18432 + so, Ql + go);
    }
    CP_COMMIT();                         // G0

    kvload(sb + KVOFF, Kh, Kl, Vh, Vl,
           (size_t)(b * SEQ) * D_MODEL + hcol, tid);
    CP_COMMIT();                         // G1

    float acco[8][4];
    #pragma unroll
    for (int i = 0; i < 8; i++)
        #pragma unroll
        for (int j = 0; j < 4; j++) acco[i][j] = 0.f;
    float m0r = -1e30f, m1r = -1e30f, l0r = 0.f, l1r = 0.f;

    const uint32_t qhT = sb, qlT = sb + 18432;

    #pragma unroll 1
    for (int kb = 0; kb < 16; kb++) {
        if (kb < 15)
            kvload(sb + KVOFF + ((kb + 1) & 1) * KVST, Kh, Kl, Vh, Vl,
                   (size_t)(b * SEQ + (kb + 1) * 64) * D_MODEL + hcol, tid);
        CP_COMMIT();
        CP_WAIT1();
        __syncthreads();

        const uint32_t kst = sb + KVOFF + (kb & 1) * KVST;
        const uint32_t khT = kst, klT = kst + KVB;
        const uint32_t vhT = kst + 2 * KVB, vlT = kst + 3 * KVB;

        // ---- S = Q K^T, 3-split ----
        float accs[8][4];
        #pragma unroll
        for (int i = 0; i < 8; i++)
            #pragma unroll
            for (int j = 0; j < 4; j++) accs[i][j] = 0.f;

        #pragma unroll
        for (int kt = 0; kt < 4; kt++) {
            uint32_t ah[4], al[4], kfh[4][4], kfl[4][4];
            ldsm_x4(ah, qhT + (wid * 16 + lr) * AST + kt * 32 + lc * 16);
            ldsm_x4(al, qlT + (wid * 16 + lr) * AST + kt * 32 + lc * 16);
            #pragma unroll
            for (int j = 0; j < 4; j++) {
                ldsm_x4(kfh[j], khT + (j * 16 + lr) * AST + kt * 32 + lc * 16);
                ldsm_x4(kfl[j], klT + (j * 16 + lr) * AST + kt * 32 + lc * 16);
            }
            #pragma unroll
            for (int j = 0; j < 4; j++) {
                mma16816(accs[2 * j],     ah, kfh[j][0], kfh[j][2]);
                mma16816(accs[2 * j + 1], ah, kfh[j][1], kfh[j][3]);
                mma16816(accs[2 * j],     ah, kfl[j][0], kfl[j][2]);
                mma16816(accs[2 * j + 1], ah, kfl[j][1], kfl[j][3]);
                mma16816(accs[2 * j],     al, kfh[j][0], kfh[j][2]);
                mma16816(accs[2 * j + 1], al, kfh[j][1], kfh[j][3]);
            }
        }

        // ---- online softmax on fragments (log2 domain) ----
        float mx0 = accs[0][0], mx1 = accs[0][2];
        #pragma unroll
        for (int nt = 0; nt < 8; nt++) {
            mx0 = fmaxf(mx0, fmaxf(accs[nt][0], accs[nt][1]));
            mx1 = fmaxf(mx1, fmaxf(accs[nt][2], accs[nt][3]));
        }
        mx0 = fmaxf(mx0, __shfl_xor_sync(0xffffffffu, mx0, 1));
        mx0 = fmaxf(mx0, __shfl_xor_sync(0xffffffffu, mx0, 2));
        mx1 = fmaxf(mx1, __shfl_xor_sync(0xffffffffu, mx1, 1));
        mx1 = fmaxf(mx1, __shfl_xor_sync(0xffffffffu, mx1, 2));
        float mn0 = fmaxf(m0r, mx0), mn1 = fmaxf(m1r, mx1);
        float al0 = ex2f(m0r - mn0), al1 = ex2f(m1r - mn1);
        m0r = mn0; m1r = mn1;
        float s0 = 0.f, s1 = 0.f;
        #pragma unroll
        for (int nt = 0; nt < 8; nt++) {
            accs[nt][0] = ex2f(accs[nt][0] - mn0);
            accs[nt][1] = ex2f(accs[nt][1] - mn0);
            accs[nt][2] = ex2f(accs[nt][2] - mn1);
            accs[nt][3] = ex2f(accs[nt][3] - mn1);
            s0 += accs[nt][0] + accs[nt][1];
            s1 += accs[nt][2] + accs[nt][3];
        }
        s0 += __shfl_xor_sync(0xffffffffu, s0, 1);
        s0 += __shfl_xor_sync(0xffffffffu, s0, 2);
        s1 += __shfl_xor_sync(0xffffffffu, s1, 1);
        s1 += __shfl_xor_sync(0xffffffffu, s1, 2);
        l0r = l0r * al0 + s0;
        l1r = l1r * al1 + s1;
        #pragma unroll
        for (int nt = 0; nt < 8; nt++) {
            acco[nt][0] *= al0; acco[nt][1] *= al0;
            acco[nt][2] *= al1; acco[nt][3] *= al1;
        }

        // ---- pack P fragments (hi/lo) ----
        uint32_t ph[4][4], pl[4][4];
        #pragma unroll
        for (int kt = 0; kt < 4; kt++) {
            ph[kt][0] = pk2(accs[2 * kt][0], accs[2 * kt][1]);
            ph[kt][1] = pk2(accs[2 * kt][2], accs[2 * kt][3]);
            ph[kt][2] = pk2(accs[2 * kt + 1][0], accs[2 * kt + 1][1]);
            ph[kt][3] = pk2(accs[2 * kt + 1][2], accs[2 * kt + 1][3]);
            float2 f0 = upk2(ph[kt][0]), f1 = upk2(ph[kt][1]);
            float2 f2 = upk2(ph[kt][2]), f3 = upk2(ph[kt][3]);
            pl[kt][0] = pk2(accs[2 * kt][0] - f0.x, accs[2 * kt][1] - f0.y);
            pl[kt][1] = pk2(accs[2 * kt][2] - f1.x, accs[2 * kt][3] - f1.y);
            pl[kt][2] = pk2(accs[2 * kt + 1][0] - f2.x, accs[2 * kt + 1][1] - f2.y);
            pl[kt][3] = pk2(accs[2 * kt + 1][2] - f3.x, accs[2 * kt + 1][3] - f3.y);
        }

        // ---- O += P V, 3-split ----
        #pragma unroll
        for (int kt = 0; kt < 4; kt++) {
            uint32_t vbh[4][4], vbl[4][4];
            #pragma unroll
            for (int cg = 0; cg < 4; cg++) {
                ldsm_x4t(vbh[cg], vhT + (kt * 16 + lr) * AST + cg * 32 + lc * 16);
                ldsm_x4t(vbl[cg], vlT + (kt * 16 + lr) * AST + cg * 32 + lc * 16);
            }
            #pragma unroll
            for (int nt = 0; nt < 8; nt++) {
                uint32_t h0 = vbh[nt >> 1][(nt & 1) * 2];
                uint32_t h1 = vbh[nt >> 1][(nt & 1) * 2 + 1];
                mma16816(acco[nt], ph[kt], h0, h1);
                mma16816(acco[nt], pl[kt], h0, h1);
                mma16816(acco[nt], ph[kt],
                         vbl[nt >> 1][(nt & 1) * 2],
                         vbl[nt >> 1][(nt & 1) * 2 + 1]);
            }
        }
        __syncthreads();   // all reads of this KV stage done before reload
    }

    // ---- epilogue: O/l -> bf16 hi/lo ----
    float inv0 = 1.f / l0r, inv1 = 1.f / l1r;
    size_t r0 = (qrow0 + wid * 16 + g) * D_MODEL + hcol;
    size_t r1 = r0 + 8 * D_MODEL;
    #pragma unroll
    for (int nt = 0; nt < 8; nt++) {
        int col = nt * 8 + tg * 2;
        float v0 = acco[nt][0] * inv0, v1 = acco[nt][1] * inv0;
        float v2 = acco[nt][2] * inv1, v3 = acco[nt][3] * inv1;
        uint32_t h01 = pk2(v0, v1), h23 = pk2(v2, v3);
        float2 f01 = upk2(h01), f23 = upk2(h23);
        *(uint32_t*)&Oh[r0 + col] = h01;
        *(uint32_t*)&Oh[r1 + col] = h23;
        *(uint32_t*)&Ol[r0 + col] = pk2(v0 - f01.x, v1 - f01.y);
        *(uint32_t*)&Ol[r1 + col] = pk2(v2 - f23.x, v3 - f23.y);
    }
}

// ============================================================
extern "C" void kernel_launch(void* const* d_in, const int* in_sizes, int n_in,
                              void* d_out, int out_size)
{
    const float* x = (const float*)d_in[0];
    const float* W[4] = {(const float*)d_in[1], (const float*)d_in[2],
                         (const float*)d_in[3], (const float*)d_in[4]};
    float* out = (float*)d_out;

    bf16 *xh, *xl, *qh, *ql, *kh, *kl, *vh, *vl, *oh, *ol, *wh[4], *wl[4];
    cudaGetSymbolAddress((void**)&xh, g_xh);
    cudaGetSymbolAddress((void**)&xl, g_xl);
    cudaGetSymbolAddress((void**)&qh, g_Qh);
    cudaGetSymbolAddress((void**)&ql, g_Ql);
    cudaGetSymbolAddress((void**)&kh, g_Kh);
    cudaGetSymbolAddress((void**)&kl, g_Kl);
    cudaGetSymbolAddress((void**)&vh, g_Vh);
    cudaGetSymbolAddress((void**)&vl, g_Vl);
    cudaGetSymbolAddress((void**)&oh, g_Oh);
    cudaGetSymbolAddress((void**)&ol, g_Ol);
    {
        bf16 *bh, *bl;
        cudaGetSymbolAddress((void**)&bh, g_Wh);
        cudaGetSymbolAddress((void**)&bl, g_Wl);
        for (int i = 0; i < 4; i++) {
            wh[i] = bh + (size_t)i * D_MODEL * D_MODEL;
            wl[i] = bl + (size_t)i * D_MODEL * D_MODEL;
        }
    }

    static int cfg_done = 0;
    if (!cfg_done) {
        cudaFuncSetAttribute(hgemm3t<0>,
            cudaFuncAttributeMaxDynamicSharedMemorySize, GEM_SMEM);
        cudaFuncSetAttribute(hgemm3t<1>,
            cudaFuncAttributeMaxDynamicSharedMemorySize, GEM_SMEM);
        cudaFuncSetAttribute(attn_mma,
            cudaFuncAttributeMaxDynamicSharedMemorySize, ATT_SMEM);
        cfg_done = 1;
    }

    fsplit<<<MROWS * D_MODEL / 1024, 256>>>(x, xh, xl);
    for (int i = 0; i < 4; i++)
        fsplit<<<D_MODEL * D_MODEL / 1024, 256>>>(W[i], wh[i], wl[i]);

    dim3 gg(D_MODEL / 128, MROWS / 256);   // (8, 32)
    const float QSC = 0.125f * 1.44269504088896f;   // fold 1/sqrt(dh)*log2(e)
    hgemm3t<1><<<gg, 256, GEM_SMEM>>>(xh, xl, wh[0], wl[0],
                                      nullptr, qh, ql, QSC);
    hgemm3t<1><<<gg, 256, GEM_SMEM>>>(xh, xl, wh[1], wl[1],
                                      nullptr, kh, kl, 1.0f);
    hgemm3t<1><<<gg, 256, GEM_SMEM>>>(xh, xl, wh[2], wl[2],
                                      nullptr, vh, vl, 1.0f);

    attn_mma<<<dim3(SEQ / 128, HEADS, BATCH), 256, ATT_SMEM>>>(
        qh, ql, kh, kl, vh, vl, oh, ol);

    hgemm3t<0><<<gg, 256, GEM_SMEM>>>(oh, ol, wh[3], wl[3],
                                      out, nullptr, nullptr, 1.0f);
}

// round 7
// speedup vs baseline: 4.0745x; 1.0031x over previous
#include <cuda_runtime.h>
#include <cuda_bf16.h>
#include <math.h>
#include <cstdint>

#define D_MODEL 1024
#define HEADS   16
#define DH      64
#define SEQ     1024
#define BATCH   8
#define MROWS   (BATCH*SEQ)   // 8192

typedef __nv_bfloat16 bf16;

// ---- scratch (no cudaMalloc allowed) ----
__device__ bf16 g_xh[MROWS*D_MODEL];
__device__ bf16 g_xl[MROWS*D_MODEL];
__device__ bf16 g_Qh[MROWS*D_MODEL];
__device__ bf16 g_Ql[MROWS*D_MODEL];
__device__ bf16 g_Kh[MROWS*D_MODEL];
__device__ bf16 g_Kl[MROWS*D_MODEL];
__device__ bf16 g_Vh[MROWS*D_MODEL];
__device__ bf16 g_Vl[MROWS*D_MODEL];
__device__ bf16 g_Oh[MROWS*D_MODEL];
__device__ bf16 g_Ol[MROWS*D_MODEL];
__device__ bf16 g_Wh[4][D_MODEL*D_MODEL];  // natural [k][n]
__device__ bf16 g_Wl[4][D_MODEL*D_MODEL];

#define QSC (0.125f * 1.44269504088896f)   // 1/sqrt(dh) * log2(e)

// ============================================================
// PTX helpers (sm_80-era only; tcgen05 unavailable at .target sm_103)
// ============================================================
__device__ __forceinline__ uint32_t smem_u32(const void* p) {
    uint32_t a;
    asm("{ .reg .u64 t; cvta.to.shared.u64 t, %1; cvt.u32.u64 %0, t; }"
        : "=r"(a) : "l"(p));
    return a;
}
__device__ __forceinline__ void cpa16(uint32_t dst, const void* src) {
    asm volatile("cp.async.cg.shared.global [%0], [%1], 16;"
                 :: "r"(dst), "l"(src) : "memory");
}
#define CP_COMMIT() asm volatile("cp.async.commit_group;" ::: "memory")
#define CP_WAIT1()  asm volatile("cp.async.wait_group 1;" ::: "memory")
#define CP_WAIT0()  asm volatile("cp.async.wait_group 0;" ::: "memory")

__device__ __forceinline__ void ldsm_x4(uint32_t* r, uint32_t addr) {
    asm volatile("ldmatrix.sync.aligned.m8n8.x4.shared.b16 {%0,%1,%2,%3}, [%4];"
                 : "=r"(r[0]), "=r"(r[1]), "=r"(r[2]), "=r"(r[3]) : "r"(addr));
}
__device__ __forceinline__ void ldsm_x4t(uint32_t* r, uint32_t addr) {
    asm volatile("ldmatrix.sync.aligned.m8n8.x4.trans.shared.b16 {%0,%1,%2,%3}, [%4];"
                 : "=r"(r[0]), "=r"(r[1]), "=r"(r[2]), "=r"(r[3]) : "r"(addr));
}
__device__ __forceinline__ void mma16816(float* c, const uint32_t* a,
                                         uint32_t b0, uint32_t b1) {
    asm volatile(
        "mma.sync.aligned.m16n8k16.row.col.f32.bf16.bf16.f32 "
        "{%0,%1,%2,%3}, {%4,%5,%6,%7}, {%8,%9}, {%0,%1,%2,%3};"
        : "+f"(c[0]), "+f"(c[1]), "+f"(c[2]), "+f"(c[3])
        : "r"(a[0]), "r"(a[1]), "r"(a[2]), "r"(a[3]), "r"(b0), "r"(b1));
}
__device__ __forceinline__ float ex2f(float x) {
    float r; asm("ex2.approx.f32 %0, %1;" : "=f"(r) : "f"(x)); return r;
}
__device__ __forceinline__ uint32_t pk2(float lo, float hi) {   // bf16x2 {lo,hi}
    uint32_t d;
    asm("cvt.rn.bf16x2.f32 %0, %1, %2;" : "=r"(d) : "f"(hi), "f"(lo));
    return d;
}
__device__ __forceinline__ float2 upk2(uint32_t v) {
    __nv_bfloat162 t = *reinterpret_cast<__nv_bfloat162*>(&v);
    return __bfloat1622float2(t);
}

// ============================================================
// splits: fp32 -> bf16 hi/lo
// ============================================================
__device__ __forceinline__ void split4(const float* __restrict__ X,
                                       bf16* __restrict__ Xh,
                                       bf16* __restrict__ Xl, size_t i) {
    float4 v = *(const float4*)&X[i];
    float a[4] = {v.x, v.y, v.z, v.w};
    bf16 h[4], l[4];
    #pragma unroll
    for (int j = 0; j < 4; j++) {
        h[j] = __float2bfloat16_rn(a[j]);
        l[j] = __float2bfloat16_rn(a[j] - __bfloat162float(h[j]));
    }
    *(__nv_bfloat162*)&Xh[i]     = __halves2bfloat162(h[0], h[1]);
    *(__nv_bfloat162*)&Xh[i + 2] = __halves2bfloat162(h[2], h[3]);
    *(__nv_bfloat162*)&Xl[i]     = __halves2bfloat162(l[0], l[1]);
    *(__nv_bfloat162*)&Xl[i + 2] = __halves2bfloat162(l[2], l[3]);
}
__global__ void fsplit(const float* __restrict__ X,
                       bf16* __restrict__ Xh, bf16* __restrict__ Xl) {
    size_t i = (size_t)(blockIdx.x * blockDim.x + threadIdx.x) * 4;
    split4(X, Xh, Xl, i);
}
__global__ void wsplit4(const float* __restrict__ w0, const float* __restrict__ w1,
                        const float* __restrict__ w2, const float* __restrict__ w3,
                        bf16* __restrict__ Wh, bf16* __restrict__ Wl) {
    int z = blockIdx.z;
    const float* W = (z == 0) ? w0 : (z == 1) ? w1 : (z == 2) ? w2 : w3;
    size_t off = (size_t)z * D_MODEL * D_MODEL;
    size_t i = (size_t)(blockIdx.x * blockDim.x + threadIdx.x) * 4;
    split4(W, Wh + off, Wl + off, i);
}

// ============================================================
// hgemm4: C[M,1024] = A @ W via bf16 3-split on mma.sync.
//   CTA 256x128, 8 warps (4m x 2n) of 64x64.
//   K-chunk of 64 loads ALL FOUR tiles (Ah,Al,Bh,Bl) once, then runs
//   3 mma sub-passes (Ah*Bh, Ah*Bl, Al*Bh). 16 chunks, double-buffered.
//   MODE 1: QKV fused via grid.z (bf16 hi/lo out, scaled).
//   MODE 0: fp32 out (final projection).
// ============================================================
#define AST 144                         // A smem row stride bytes (72 bf16)
#define BST 272                         // B smem row stride bytes (136 bf16)
#define ABYT (256 * AST)                // 36864
#define BBYT (64 * BST)                 // 17408
#define STG4 (2 * ABYT + 2 * BBYT)      // 108544
#define GEM_SMEM (2 * STG4)             // 217088

__device__ __forceinline__ void gload4(uint32_t st,
    const bf16* __restrict__ Ah, const bf16* __restrict__ Al,
    const bf16* __restrict__ Bh, const bf16* __restrict__ Bl,
    int m0, int n0, int kk0, int tid)
{
    #pragma unroll
    for (int t = 0; t < 8; t++) {            // A: 256x64, hi+lo
        int idx = tid + (t << 8);
        int r = idx >> 3, c = idx & 7;
        size_t go = (size_t)(m0 + r) * D_MODEL + kk0 + c * 8;
        uint32_t so = st + r * AST + c * 16;
        cpa16(so, Ah + go);
        cpa16(so + ABYT, Al + go);
    }
    #pragma unroll
    for (int t = 0; t < 4; t++) {            // B: 64x128, hi+lo
        int idx = tid + (t << 8);
        int r = idx >> 4, c = idx & 15;
        size_t go = (size_t)(kk0 + r) * D_MODEL + n0 + c * 8;
        uint32_t so = st + 2 * ABYT + r * BST + c * 16;
        cpa16(so, Bh + go);
        cpa16(so + BBYT, Bl + go);
    }
}

__device__ __forceinline__ void gpass(float acc[32][4], uint32_t aT, uint32_t bT,
                                      int wm, int wn, int lr, int lc)
{
    #pragma unroll
    for (int k16 = 0; k16 < 4; k16++) {
        uint32_t a[4][4], b[4][4];
        #pragma unroll
        for (int mt = 0; mt < 4; mt++)
            ldsm_x4(a[mt], aT + (wm * 64 + mt * 16 + lr) * AST + k16 * 32 + lc * 16);
        #pragma unroll
        for (int cg = 0; cg < 4; cg++)
            ldsm_x4t(b[cg], bT + (k16 * 16 + lr) * BST + wn * 128 + cg * 32 + lc * 16);
        #pragma unroll
        for (int mt = 0; mt < 4; mt++)
            #pragma unroll
            for (int nt = 0; nt < 8; nt++)
                mma16816(acc[mt * 8 + nt], a[mt],
                         b[nt >> 1][(nt & 1) * 2], b[nt >> 1][(nt & 1) * 2 + 1]);
    }
}

template<int MODE>
__global__ __launch_bounds__(256) void hgemm4(
    const bf16* __restrict__ Ah, const bf16* __restrict__ Al,
    const bf16* __restrict__ BhB, const bf16* __restrict__ BlB,
    float* __restrict__ C,
    bf16* __restrict__ Ch0, bf16* __restrict__ Cl0,
    bf16* __restrict__ Ch1, bf16* __restrict__ Cl1,
    bf16* __restrict__ Ch2, bf16* __restrict__ Cl2)
{
    extern __shared__ char dsm[];
    const uint32_t sb = smem_u32(dsm);

    const int tid = threadIdx.x;
    const int wid = tid >> 5;
    const int lane = tid & 31;
    const int wm = wid >> 1, wn = wid & 1;
    const int lr = lane & 15, lc = lane >> 4;
    const int m0 = blockIdx.y << 8;
    const int n0 = blockIdx.x << 7;
    const int z  = blockIdx.z;

    const bf16* Bh = BhB + (size_t)z * D_MODEL * D_MODEL;
    const bf16* Bl = BlB + (size_t)z * D_MODEL * D_MODEL;

    float acc[32][4];
    #pragma unroll
    for (int i = 0; i < 32; i++)
        #pragma unroll
        for (int j = 0; j < 4; j++) acc[i][j] = 0.f;

    gload4(sb, Ah, Al, Bh, Bl, m0, n0, 0, tid);
    CP_COMMIT();

    #pragma unroll 1
    for (int s = 0; s < 16; s++) {
        if (s < 15) {
            gload4(sb + ((s + 1) & 1) * STG4, Ah, Al, Bh, Bl,
                   m0, n0, (s + 1) << 6, tid);
            CP_COMMIT();
            CP_WAIT1();
        } else {
            CP_WAIT0();
        }
        __syncthreads();

        const uint32_t aH = sb + (s & 1) * STG4;
        const uint32_t aL = aH + ABYT;
        const uint32_t bH = aH + 2 * ABYT;
        const uint32_t bL = bH + BBYT;
        gpass(acc, aH, bH, wm, wn, lr, lc);
        gpass(acc, aH, bL, wm, wn, lr, lc);
        gpass(acc, aL, bH, wm, wn, lr, lc);
        __syncthreads();
    }

    const int g = lane >> 2, tg = lane & 3;
    const float scale = (MODE == 1 && z == 0) ? QSC : 1.0f;
    bf16* Ch = (z == 0) ? Ch0 : (z == 1) ? Ch1 : Ch2;
    bf16* Cl = (z == 0) ? Cl0 : (z == 1) ? Cl1 : Cl2;

    #pragma unroll
    for (int mt = 0; mt < 4; mt++) {
        int row = m0 + wm * 64 + mt * 16 + g;
        #pragma unroll
        for (int nt = 0; nt < 8; nt++) {
            int col = n0 + wn * 64 + nt * 8 + tg * 2;
            float* ac = acc[mt * 8 + nt];
            if (MODE == 0) {
                float* cp = &C[(size_t)row * D_MODEL + col];
                *(float2*)cp = make_float2(ac[0], ac[1]);
                *(float2*)(cp + 8 * D_MODEL) = make_float2(ac[2], ac[3]);
            } else {
                float v0 = ac[0] * scale, v1 = ac[1] * scale;
                float v2 = ac[2] * scale, v3 = ac[3] * scale;
                uint32_t h01 = pk2(v0, v1), h23 = pk2(v2, v3);
                float2 f01 = upk2(h01), f23 = upk2(h23);
                size_t o0 = (size_t)row * D_MODEL + col;
                size_t o1 = o0 + 8 * D_MODEL;
                *(uint32_t*)&Ch[o0] = h01;
                *(uint32_t*)&Ch[o1] = h23;
                *(uint32_t*)&Cl[o0] = pk2(v0 - f01.x, v1 - f01.y);
                *(uint32_t*)&Cl[o1] = pk2(v2 - f23.x, v3 - f23.y);
            }
        }
    }
}

// ============================================================
// attn_mma2: flash attention on mma.sync, bf16 3-split both GEMMs.
//   CTA = 256 queries x (head, batch), 8 warps x 32 q-rows each.
//   K/V fragment loads amortized over 2x mma vs R6.
//   P packed per-kt in registers (never hits smem).
// ============================================================
#define QTB  (256 * AST)                 // one 256x64 bf16 Q tile = 36864
#define KVB  (64 * AST)                  // one 64x64 bf16 tile = 9216
#define KVST (4 * KVB)                   // Kh,Kl,Vh,Vl per stage = 36864
#define KVOFF (2 * QTB)                  // 73728
#define ATT_SMEM (KVOFF + 2 * KVST)      // 147456

__device__ __forceinline__ void kvload(uint32_t st,
    const bf16* __restrict__ Kh, const bf16* __restrict__ Kl,
    const bf16* __restrict__ Vh, const bf16* __restrict__ Vl,
    size_t gbase, int tid)
{
    #pragma unroll
    for (int t = 0; t < 2; t++) {
        int idx = tid + (t << 8);
        int r = idx >> 3, c = idx & 7;
        size_t go = gbase + (size_t)r * D_MODEL + c * 8;
        uint32_t so = st + r * AST + c * 16;
        cpa16(so,           Kh + go);
        cpa16(so + KVB,     Kl + go);
        cpa16(so + 2 * KVB, Vh + go);
        cpa16(so + 3 * KVB, Vl + go);
    }
}

__global__ __launch_bounds__(256, 1) void attn_mma2(
    const bf16* __restrict__ Qh, const bf16* __restrict__ Ql,
    const bf16* __restrict__ Kh, const bf16* __restrict__ Kl,
    const bf16* __restrict__ Vh, const bf16* __restrict__ Vl,
    bf16* __restrict__ Oh, bf16* __restrict__ Ol)
{
    extern __shared__ char dsm[];
    const uint32_t sb = smem_u32(dsm);

    const int tid = threadIdx.x;
    const int wid = tid >> 5;
    const int lane = tid & 31;
    const int lr = lane & 15, lc = lane >> 4;
    const int g = lane >> 2, tg = lane & 3;
    const int qb = blockIdx.x, h = blockIdx.y, b = blockIdx.z;
    const size_t qrow0 = (size_t)(b * SEQ + qb * 256);
    const size_t hcol = h * DH;

    // ---- load Q tiles (256x64 hi + lo) ----
    #pragma unroll
    for (int t = 0; t < 8; t++) {
        int idx = tid + (t << 8);
        int r = idx >> 3, c = idx & 7;
        size_t go = (qrow0 + r) * D_MODEL + hcol + c * 8;
        uint32_t so = sb + r * AST + c * 16;
        cpa16(so, Qh + go);
        cpa16(so + QTB, Ql + go);
    }
    CP_COMMIT();

    kvload(sb + KVOFF, Kh, Kl, Vh, Vl, (size_t)(b * SEQ) * D_MODEL + hcol, tid);
    CP_COMMIT();

    float acco[16][4];
    #pragma unroll
    for (int i = 0; i < 16; i++)
        #pragma unroll
        for (int j = 0; j < 4; j++) acco[i][j] = 0.f;
    float mrow[4] = {-1e30f, -1e30f, -1e30f, -1e30f};
    float lrow[4] = {0.f, 0.f, 0.f, 0.f};

    #pragma unroll 1
    for (int kb = 0; kb < 16; kb++) {
        if (kb < 15)
            kvload(sb + KVOFF + ((kb + 1) & 1) * KVST, Kh, Kl, Vh, Vl,
                   (size_t)(b * SEQ + (kb + 1) * 64) * D_MODEL + hcol, tid);
        CP_COMMIT();
        CP_WAIT1();
        __syncthreads();

        const uint32_t kst = sb + KVOFF + (kb & 1) * KVST;
        const uint32_t khT = kst, klT = kst + KVB;
        const uint32_t vhT = kst + 2 * KVB, vlT = kst + 3 * KVB;

        // ---- S = Q K^T, 3-split; accs[mt*8+nt][c] ----
        float accs[16][4];
        #pragma unroll
        for (int i = 0; i < 16; i++)
            #pragma unroll
            for (int j = 0; j < 4; j++) accs[i][j] = 0.f;

        #pragma unroll
        for (int kt = 0; kt < 4; kt++) {
            uint32_t ah[2][4], al[2][4], kfh[4][4], kfl[4][4];
            #pragma unroll
            for (int mt = 0; mt < 2; mt++) {
                uint32_t qoff = (wid * 32 + mt * 16 + lr) * AST + kt * 32 + lc * 16;
                ldsm_x4(ah[mt], sb + qoff);
                ldsm_x4(al[mt], sb + QTB + qoff);
            }
            #pragma unroll
            for (int j = 0; j < 4; j++) {
                uint32_t koff = (j * 16 + lr) * AST + kt * 32 + lc * 16;
                ldsm_x4(kfh[j], khT + koff);
                ldsm_x4(kfl[j], klT + koff);
            }
            #pragma unroll
            for (int mt = 0; mt < 2; mt++)
                #pragma unroll
                for (int j = 0; j < 4; j++) {
                    float* c0 = accs[mt * 8 + 2 * j];
                    float* c1 = accs[mt * 8 + 2 * j + 1];
                    mma16816(c0, ah[mt], kfh[j][0], kfh[j][2]);
                    mma16816(c1, ah[mt], kfh[j][1], kfh[j][3]);
                    mma16816(c0, ah[mt], kfl[j][0], kfl[j][2]);
                    mma16816(c1, ah[mt], kfl[j][1], kfl[j][3]);
                    mma16816(c0, al[mt], kfh[j][0], kfh[j][2]);
                    mma16816(c1, al[mt], kfh[j][1], kfh[j][3]);
                }
        }

        // ---- online softmax on fragments (log2 domain), per mt ----
        #pragma unroll
        for (int mt = 0; mt < 2; mt++) {
            float mx0 = -1e30f, mx1 = -1e30f;
            #pragma unroll
            for (int nt = 0; nt < 8; nt++) {
                mx0 = fmaxf(mx0, fmaxf(accs[mt * 8 + nt][0], accs[mt * 8 + nt][1]));
                mx1 = fmaxf(mx1, fmaxf(accs[mt * 8 + nt][2], accs[mt * 8 + nt][3]));
            }
            mx0 = fmaxf(mx0, __shfl_xor_sync(0xffffffffu, mx0, 1));
            mx0 = fmaxf(mx0, __shfl_xor_sync(0xffffffffu, mx0, 2));
            mx1 = fmaxf(mx1, __shfl_xor_sync(0xffffffffu, mx1, 1));
            mx1 = fmaxf(mx1, __shfl_xor_sync(0xffffffffu, mx1, 2));
            float mn0 = fmaxf(mrow[mt * 2],     mx0);
            float mn1 = fmaxf(mrow[mt * 2 + 1], mx1);
            float al0 = ex2f(mrow[mt * 2]     - mn0);
            float al1 = ex2f(mrow[mt * 2 + 1] - mn1);
            mrow[mt * 2] = mn0; mrow[mt * 2 + 1] = mn1;
            float s0 = 0.f, s1 = 0.f;
            #pragma unroll
            for (int nt = 0; nt < 8; nt++) {
                float* a = accs[mt * 8 + nt];
                a[0] = ex2f(a[0] - mn0);
                a[1] = ex2f(a[1] - mn0);
                a[2] = ex2f(a[2] - mn1);
                a[3] = ex2f(a[3] - mn1);
                s0 += a[0] + a[1];
                s1 += a[2] + a[3];
            }
            s0 += __shfl_xor_sync(0xffffffffu, s0, 1);
            s0 += __shfl_xor_sync(0xffffffffu, s0, 2);
            s1 += __shfl_xor_sync(0xffffffffu, s1, 1);
            s1 += __shfl_xor_sync(0xffffffffu, s1, 2);
            lrow[mt * 2]     = lrow[mt * 2]     * al0 + s0;
            lrow[mt * 2 + 1] = lrow[mt * 2 + 1] * al1 + s1;
            #pragma unroll
            for (int nt = 0; nt < 8; nt++) {
                acco[mt * 8 + nt][0] *= al0; acco[mt * 8 + nt][1] *= al0;
                acco[mt * 8 + nt][2] *= al1; acco[mt * 8 + nt][3] *= al1;
            }
        }

        // ---- O += P V, 3-split; P packed per-kt (accs dies as packs born) ----
        #pragma unroll
        for (int kt = 0; kt < 4; kt++) {
            uint32_t vbh[4][4], vbl[4][4];
            #pragma unroll
            for (int cg = 0; cg < 4; cg++) {
                uint32_t voff = (kt * 16 + lr) * AST + cg * 32 + lc * 16;
                ldsm_x4t(vbh[cg], vhT + voff);
                ldsm_x4t(vbl[cg], vlT + voff);
            }
            #pragma unroll
            for (int mt = 0; mt < 2; mt++) {
                float* s0 = accs[mt * 8 + 2 * kt];
                float* s1 = accs[mt * 8 + 2 * kt + 1];
                uint32_t ph[4], pl[4];
                ph[0] = pk2(s0[0], s0[1]);
                ph[1] = pk2(s0[2], s0[3]);
                ph[2] = pk2(s1[0], s1[1]);
                ph[3] = pk2(s1[2], s1[3]);
                float2 f0 = upk2(ph[0]), f1 = upk2(ph[1]);
                float2 f2 = upk2(ph[2]), f3 = upk2(ph[3]);
                pl[0] = pk2(s0[0] - f0.x, s0[1] - f0.y);
                pl[1] = pk2(s0[2] - f1.x, s0[3] - f1.y);
                pl[2] = pk2(s1[0] - f2.x, s1[1] - f2.y);
                pl[3] = pk2(s1[2] - f3.x, s1[3] - f3.y);
                #pragma unroll
                for (int nt = 0; nt < 8; nt++) {
                    uint32_t h0 = vbh[nt >> 1][(nt & 1) * 2];
                    uint32_t h1 = vbh[nt >> 1][(nt & 1) * 2 + 1];
                    mma16816(acco[mt * 8 + nt], ph, h0, h1);
                    mma16816(acco[mt * 8 + nt], pl, h0, h1);
                    mma16816(acco[mt * 8 + nt], ph,
                             vbl[nt >> 1][(nt & 1) * 2],
                             vbl[nt >> 1][(nt & 1) * 2 + 1]);
                }
            }
        }
        __syncthreads();
    }

    // ---- epilogue: O/l -> bf16 hi/lo ----
    #pragma unroll
    for (int mt = 0; mt < 2; mt++) {
        float inv0 = 1.f / lrow[mt * 2];
        float inv1 = 1.f / lrow[mt * 2 + 1];
        size_t r0 = (qrow0 + wid * 32 + mt * 16 + g) * D_MODEL + hcol;
        size_t r1 = r0 + 8 * D_MODEL;
        #pragma unroll
        for (int nt = 0; nt < 8; nt++) {
            int col = nt * 8 + tg * 2;
            float v0 = acco[mt * 8 + nt][0] * inv0;
            float v1 = acco[mt * 8 + nt][1] * inv0;
            float v2 = acco[mt * 8 + nt][2] * inv1;
            float v3 = acco[mt * 8 + nt][3] * inv1;
            uint32_t h01 = pk2(v0, v1), h23 = pk2(v2, v3);
            float2 f01 = upk2(h01), f23 = upk2(h23);
            *(uint32_t*)&Oh[r0 + col] = h01;
            *(uint32_t*)&Oh[r1 + col] = h23;
            *(uint32_t*)&Ol[r0 + col] = pk2(v0 - f01.x, v1 - f01.y);
            *(uint32_t*)&Ol[r1 + col] = pk2(v2 - f23.x, v3 - f23.y);
        }
    }
}

// ============================================================
extern "C" void kernel_launch(void* const* d_in, const int* in_sizes, int n_in,
                              void* d_out, int out_size)
{
    const float* x = (const float*)d_in[0];
    float* out = (float*)d_out;

    bf16 *xh, *xl, *qh, *ql, *kh, *kl, *vh, *vl, *oh, *ol, *bh, *bl;
    cudaGetSymbolAddress((void**)&xh, g_xh);
    cudaGetSymbolAddress((void**)&xl, g_xl);
    cudaGetSymbolAddress((void**)&qh, g_Qh);
    cudaGetSymbolAddress((void**)&ql, g_Ql);
    cudaGetSymbolAddress((void**)&kh, g_Kh);
    cudaGetSymbolAddress((void**)&kl, g_Kl);
    cudaGetSymbolAddress((void**)&vh, g_Vh);
    cudaGetSymbolAddress((void**)&vl, g_Vl);
    cudaGetSymbolAddress((void**)&oh, g_Oh);
    cudaGetSymbolAddress((void**)&ol, g_Ol);
    cudaGetSymbolAddress((void**)&bh, g_Wh);
    cudaGetSymbolAddress((void**)&bl, g_Wl);
    const size_t WSTR = (size_t)D_MODEL * D_MODEL;

    static int cfg_done = 0;
    if (!cfg_done) {
        cudaFuncSetAttribute(hgemm4<0>,
            cudaFuncAttributeMaxDynamicSharedMemorySize, GEM_SMEM);
        cudaFuncSetAttribute(hgemm4<1>,
            cudaFuncAttributeMaxDynamicSharedMemorySize, GEM_SMEM);
        cudaFuncSetAttribute(attn_mma2,
            cudaFuncAttributeMaxDynamicSharedMemorySize, ATT_SMEM);
        cfg_done = 1;
    }

    // splits: x, then all 4 weights in one launch
    fsplit<<<MROWS * D_MODEL / 1024, 256>>>(x, xh, xl);
    wsplit4<<<dim3(D_MODEL * D_MODEL / 1024, 1, 4), 256>>>(
        (const float*)d_in[1], (const float*)d_in[2],
        (const float*)d_in[3], (const float*)d_in[4], bh, bl);

    // QKV projections fused into one launch (grid.z selects W / output)
    hgemm4<1><<<dim3(D_MODEL / 128, MROWS / 256, 3), 256, GEM_SMEM>>>(
        xh, xl, bh, bl, nullptr, qh, ql, kh, kl, vh, vl);

    attn_mma2<<<dim3(SEQ / 256, HEADS, BATCH), 256, ATT_SMEM>>>(
        qh, ql, kh, kl, vh, vl, oh, ol);

    // final projection (W index 3)
    hgemm4<0><<<dim3(D_MODEL / 128, MROWS / 256, 1), 256, GEM_SMEM>>>(
        oh, ol, bh + 3 * WSTR, bl + 3 * WSTR, out,
        nullptr, nullptr, nullptr, nullptr, nullptr, nullptr);
}